// round 3
// baseline (speedup 1.0000x reference)
#include <cuda_runtime.h>
#include <cuda_bf16.h>
#include <mma.h>
#include <math.h>

using namespace nvcuda;

#define DM    1024
#define NIMU  72
#define NOUT  864
#define NPAD  896
#define SEQ_MAX 4096

__device__ __nv_bfloat16 g_xn_hi[SEQ_MAX * DM];
__device__ __nv_bfloat16 g_xn_lo[SEQ_MAX * DM];
__device__ __nv_bfloat16 g_w_hi[DM * NPAD];
__device__ __nv_bfloat16 g_w_lo[DM * NPAD];
__device__ float         g_p[SEQ_MAX * NPAD];
__device__ float         g_osc[SEQ_MAX * NIMU * 8];

__global__ void zero_kernel(float* __restrict__ out, int n) {
    int i = blockIdx.x * blockDim.x + threadIdx.x;
    if (i < n) out[i] = 0.0f;
}

// -------- LayerNorm + bf16 hi/lo split --------
__global__ __launch_bounds__(256) void ln_kernel(const float* __restrict__ x,
                                                 const float* __restrict__ gamma,
                                                 const float* __restrict__ beta) {
    int s = blockIdx.x, tid = threadIdx.x;
    const float4* xr = (const float4*)(x + (size_t)s * DM);
    float4 v = xr[tid];
    float sum = v.x + v.y + v.z + v.w;
    float sq  = v.x*v.x + v.y*v.y + v.z*v.z + v.w*v.w;
#pragma unroll
    for (int o = 16; o > 0; o >>= 1) {
        sum += __shfl_xor_sync(0xffffffffu, sum, o);
        sq  += __shfl_xor_sync(0xffffffffu, sq,  o);
    }
    __shared__ float ssum[8], ssq[8], s_mu, s_rs;
    int wid = tid >> 5, lane = tid & 31;
    if (lane == 0) { ssum[wid] = sum; ssq[wid] = sq; }
    __syncthreads();
    if (tid == 0) {
        float ts = 0.f, tq = 0.f;
#pragma unroll
        for (int i = 0; i < 8; i++) { ts += ssum[i]; tq += ssq[i]; }
        float mu  = ts * (1.0f / DM);
        float var = tq * (1.0f / DM) - mu * mu;
        s_mu = mu; s_rs = rsqrtf(var + 1e-5f);
    }
    __syncthreads();
    float mu = s_mu, rs = s_rs;
    size_t base = (size_t)s * DM + (size_t)tid * 4;
    float xv[4] = {v.x, v.y, v.z, v.w};
#pragma unroll
    for (int j = 0; j < 4; j++) {
        int c = tid * 4 + j;
        float xn = (xv[j] - mu) * rs * gamma[c] + beta[c];
        __nv_bfloat16 hi = __float2bfloat16(xn);
        g_xn_hi[base + j] = hi;
        g_xn_lo[base + j] = __float2bfloat16(xn - __bfloat162float(hi));
    }
}

// -------- W pad + split --------
__global__ void wsplit_kernel(const float* __restrict__ W) {
    int idx = blockIdx.x * blockDim.x + threadIdx.x;
    if (idx >= DM * NPAD) return;
    int k = idx / NPAD, n = idx - k * NPAD;
    float w = (n < NOUT) ? W[k * NOUT + n] : 0.0f;
    __nv_bfloat16 hi = __float2bfloat16(w);
    g_w_hi[idx] = hi;
    g_w_lo[idx] = __float2bfloat16(w - __bfloat162float(hi));
}

// -------- 3-split bf16 wmma GEMM: g_p = Xn * W --------
#define SAP 48
#define SBP 144
__global__ __launch_bounds__(256) void gemm_kernel() {
    __shared__ __align__(16) __nv_bfloat16 sAh[128 * SAP];
    __shared__ __align__(16) __nv_bfloat16 sAl[128 * SAP];
    __shared__ __align__(16) __nv_bfloat16 sBh[32 * SBP];
    __shared__ __align__(16) __nv_bfloat16 sBl[32 * SBP];
    int tid = threadIdx.x, wid = tid >> 5;
    int wm = wid & 3, wn = wid >> 2;
    int bm = blockIdx.x * 128, bn = blockIdx.y * 128;

    wmma::fragment<wmma::accumulator, 16, 16, 16, float> c[2][4];
#pragma unroll
    for (int i = 0; i < 2; i++)
#pragma unroll
        for (int j = 0; j < 4; j++) wmma::fill_fragment(c[i][j], 0.0f);

    int ar = tid >> 1, ac = (tid & 1) * 16;
    int br = tid >> 3, bc = (tid & 7) * 16;

    for (int kc = 0; kc < DM; kc += 32) {
        const uint4* gah = (const uint4*)(g_xn_hi + (size_t)(bm + ar) * DM + kc + ac);
        const uint4* gal = (const uint4*)(g_xn_lo + (size_t)(bm + ar) * DM + kc + ac);
        *(uint4*)(sAh + ar * SAP + ac)     = gah[0];
        *(uint4*)(sAh + ar * SAP + ac + 8) = gah[1];
        *(uint4*)(sAl + ar * SAP + ac)     = gal[0];
        *(uint4*)(sAl + ar * SAP + ac + 8) = gal[1];
        const uint4* gbh = (const uint4*)(g_w_hi + (size_t)(kc + br) * NPAD + bn + bc);
        const uint4* gbl = (const uint4*)(g_w_lo + (size_t)(kc + br) * NPAD + bn + bc);
        *(uint4*)(sBh + br * SBP + bc)     = gbh[0];
        *(uint4*)(sBh + br * SBP + bc + 8) = gbh[1];
        *(uint4*)(sBl + br * SBP + bc)     = gbl[0];
        *(uint4*)(sBl + br * SBP + bc + 8) = gbl[1];
        __syncthreads();
#pragma unroll
        for (int ks = 0; ks < 32; ks += 16) {
            wmma::fragment<wmma::matrix_a, 16, 16, 16, __nv_bfloat16, wmma::row_major> ah[2], al[2];
            wmma::fragment<wmma::matrix_b, 16, 16, 16, __nv_bfloat16, wmma::row_major> bh[4], bl[4];
#pragma unroll
            for (int i = 0; i < 2; i++) {
                wmma::load_matrix_sync(ah[i], sAh + (wm * 32 + i * 16) * SAP + ks, SAP);
                wmma::load_matrix_sync(al[i], sAl + (wm * 32 + i * 16) * SAP + ks, SAP);
            }
#pragma unroll
            for (int j = 0; j < 4; j++) {
                wmma::load_matrix_sync(bh[j], sBh + ks * SBP + wn * 64 + j * 16, SBP);
                wmma::load_matrix_sync(bl[j], sBl + ks * SBP + wn * 64 + j * 16, SBP);
            }
#pragma unroll
            for (int i = 0; i < 2; i++)
#pragma unroll
                for (int j = 0; j < 4; j++) {
                    wmma::mma_sync(c[i][j], ah[i], bh[j], c[i][j]);
                    wmma::mma_sync(c[i][j], ah[i], bl[j], c[i][j]);
                    wmma::mma_sync(c[i][j], al[i], bh[j], c[i][j]);
                }
        }
        __syncthreads();
    }
#pragma unroll
    for (int i = 0; i < 2; i++)
#pragma unroll
        for (int j = 0; j < 4; j++)
            wmma::store_matrix_sync(g_p + (size_t)(bm + wm * 32 + i * 16) * NPAD + bn + wn * 64 + j * 16,
                                    c[i][j], NPAD, wmma::mem_row_major);
}

// -------- param transform --------
__device__ __forceinline__ float softplusf(float x) {
    return (x > 20.0f) ? x : log1pf(expf(x));
}

__global__ void transform_kernel(const float* __restrict__ bias, float* __restrict__ out, int seq) {
    int t = blockIdx.x * blockDim.x + threadIdx.x;
    if (t >= seq * NIMU) return;
    int s = t / NIMU, imu = t - s * NIMU;
    float p[12];
#pragma unroll
    for (int n = 0; n < 12; n++)
        p[n] = g_p[(size_t)s * NPAD + n * NIMU + imu] + bias[n * NIMU + imu];

    float d1 = softplusf(p[1]);
    float w1 = sqrtf(softplusf(p[0]));   // sqrt(4k - d^2)/2 == sqrt(softplus(p0))
    float d2 = softplusf(p[3]);
    float w2 = sqrtf(softplusf(p[2]));
    float E1 = expf(-0.5f * d1), E2 = expf(-0.5f * d2);
    float sw1, cw1, sw2, cw2, sp1, cp1, sp2, cp2;
    sincosf(w1, &sw1, &cw1);
    sincosf(w2, &sw2, &cw2);
    sincosf(p[6], &sp1, &cp1);
    sincosf(p[7], &sp2, &cp2);

    float4 u = make_float4(E1 * cw1, E1 * sw1, p[4] * sp1, p[4] * cp1);
    float4 v = make_float4(E2 * cw2, E2 * sw2, p[5] * sp2, p[5] * cp2);
    float4* dst = (float4*)(g_osc + (size_t)t * 8);
    dst[0] = u;
    dst[1] = v;

    size_t SL = (size_t)seq, sec = (size_t)NIMU * SL;
    out[1 * sec + (size_t)imu * SL + s] = p[8];
    out[2 * sec + (size_t)imu * SL + s] = softplusf(p[9]);
    out[3 * sec + (size_t)imu * SL + s] = p[10];
    out[4 * sec + (size_t)imu * SL + s] = softplusf(p[11]);
}

// -------- oscillator + rotating-accumulator diagonal scatter --------
__global__ __launch_bounds__(256) void osc_kernel(float* __restrict__ out, int seq, int tsteps) {
    int chunks = seq >> 8;
    int imu = blockIdx.x / chunks;
    int ch  = blockIdx.x - imu * chunks;
    int lane = threadIdx.x & 31;
    int B = ch * 256 + (threadIdx.x >> 5) * 32;
    int s = B + lane;

    const float4* oc = (const float4*)(g_osc + ((size_t)s * NIMU + imu) * 8);
    float4 u = oc[0], v = oc[1];
    float a1 = u.x, b1 = u.y, S1 = u.z, C1 = u.w;
    float a2 = v.x, b2 = v.y, S2 = v.z, C2 = v.w;
    float nb1 = -b1, nb2 = -b2;
    float acc = 0.0f;
    float* kout = out + (size_t)imu * seq;

#pragma unroll 4
    for (int t = 0; t < tsteps; t++) {
        acc += S1;
        acc += S2;
        float Sn1 = fmaf(a1, S1, b1 * C1);
        C1 = fmaf(nb1, S1, a1 * C1);
        S1 = Sn1;
        float Sn2 = fmaf(a2, S2, b2 * C2);
        C2 = fmaf(nb2, S2, a2 * C2);
        S2 = Sn2;
        int pos = B + t;
        if (lane == 0) {
            if (pos < seq) atomicAdd(kout + pos, acc);
            acc = 0.0f;
        }
        acc = __shfl_sync(0xffffffffu, acc, (lane + 1) & 31);
    }
    int pos = B + tsteps + lane;
    if (pos < seq && acc != 0.0f) atomicAdd(kout + pos, acc);
}

extern "C" void kernel_launch(void* const* d_in, const int* in_sizes, int n_in,
                              void* d_out, int out_size) {
    const float* x     = (const float*)d_in[0];
    const float* gamma = (const float*)d_in[1];
    const float* beta  = (const float*)d_in[2];
    const float* W     = (const float*)d_in[3];
    const float* b     = (const float*)d_in[4];
    float* out = (float*)d_out;

    int seq = in_sizes[0] / DM;
    int tsteps = seq < 300 ? seq : 300;

    zero_kernel<<<(NIMU * seq + 255) / 256, 256>>>(out, NIMU * seq);
    ln_kernel<<<seq, 256>>>(x, gamma, beta);
    wsplit_kernel<<<(DM * NPAD + 255) / 256, 256>>>(W);
    dim3 gg(seq / 128, NPAD / 128);
    gemm_kernel<<<gg, 256>>>();
    transform_kernel<<<(seq * NIMU + 255) / 256, 256>>>(b, out, seq);
    osc_kernel<<<NIMU * (seq / 256), 256>>>(out, seq, tsteps);
}